// round 4
// baseline (speedup 1.0000x reference)
#include <cuda_runtime.h>
#include <cuda_bf16.h>

#define N_MAX 100000
#define E_MAX 1600000
#define D 128

// Scratch (allocation-free rule: __device__ globals)
__device__ int   g_deg[N_MAX];
__device__ int   g_off[N_MAX + 1];
__device__ int   g_cur[N_MAX];
__device__ int   g_src[E_MAX];
__device__ float g_dinv[N_MAX];
__device__ float g_y[(size_t)N_MAX * D];   // 51.2 MB, L2-resident working set

// ---------------------------------------------------------------- deg zero
__global__ void k_zero_deg(int n) {
    int i = blockIdx.x * blockDim.x + threadIdx.x;
    if (i < n) g_deg[i] = 0;
}

// ---------------------------------------------------------------- deg count
__global__ void k_count(const int* __restrict__ col, int E) {
    int e = blockIdx.x * blockDim.x + threadIdx.x;
    if (e < E) atomicAdd(&g_deg[col[e]], 1);
}

// ---------------------------------------------------------------- exclusive scan (single block, warp shuffles)
__global__ void k_scan(int n) {
    __shared__ int warpsum[32];
    __shared__ int carry_s;
    int tid = threadIdx.x, lane = tid & 31, w = tid >> 5;
    if (tid == 0) carry_s = 0;
    __syncthreads();
    for (int base = 0; base < n; base += 1024) {
        int i = base + tid;
        int c = carry_s;
        int v = (i < n) ? g_deg[i] : 0;
        int inc = v;
        #pragma unroll
        for (int s = 1; s < 32; s <<= 1) {
            int t = __shfl_up_sync(0xffffffffu, inc, s);
            if (lane >= s) inc += t;
        }
        if (lane == 31) warpsum[w] = inc;
        __syncthreads();
        if (w == 0) {
            int s = warpsum[lane];
            #pragma unroll
            for (int st = 1; st < 32; st <<= 1) {
                int t = __shfl_up_sync(0xffffffffu, s, st);
                if (lane >= st) s += t;
            }
            warpsum[lane] = s;
        }
        __syncthreads();
        int wbase = (w > 0) ? warpsum[w - 1] : 0;
        int incl = inc + wbase;
        if (i < n) {
            int ex = c + incl - v;
            g_off[i] = ex;
            g_cur[i] = ex;
        }
        __syncthreads();
        if (tid == 0) carry_s = c + warpsum[31];
        __syncthreads();
    }
    if (threadIdx.x == 0) g_off[n] = carry_s;
}

// ---------------------------------------------------------------- bucket fill (CSR by destination)
__global__ void k_fill(const int* __restrict__ row, const int* __restrict__ col, int E) {
    int e = blockIdx.x * blockDim.x + threadIdx.x;
    if (e < E) {
        int c = col[e];
        int pos = atomicAdd(&g_cur[c], 1);
        g_src[pos] = row[e];
    }
}

// ---------------------------------------------------------------- dinv = rsqrt(deg + 1 selfloop)
__global__ void k_dinv(int n) {
    int i = blockIdx.x * blockDim.x + threadIdx.x;
    if (i < n) g_dinv[i] = rsqrtf((float)(g_deg[i] + 1));
}

// ---------------------------------------------------------------- y = (x @ W) * dinv[row]
// 32 rows per 128-thread block; thread t owns output column t.
__global__ void k_gemm(const float* __restrict__ x, const float* __restrict__ W, int n) {
    __shared__ float xs[32 * D];
    int r0 = blockIdx.x * 32;
    int tid = threadIdx.x;

    for (int idx = tid; idx < 32 * D; idx += 128) {
        int r = idx >> 7, k = idx & 127;
        int node = r0 + r;
        xs[idx] = (node < n) ? x[(size_t)node * D + k] : 0.f;
    }
    __syncthreads();

    float acc[32];
    #pragma unroll
    for (int r = 0; r < 32; r++) acc[r] = 0.f;

    for (int k = 0; k < D; k += 4) {
        float w0 = W[(k + 0) * D + tid];
        float w1 = W[(k + 1) * D + tid];
        float w2 = W[(k + 2) * D + tid];
        float w3 = W[(k + 3) * D + tid];
        #pragma unroll
        for (int r = 0; r < 32; r++) {
            float4 xv = *reinterpret_cast<const float4*>(&xs[r * D + k]);
            acc[r] = fmaf(xv.x, w0, acc[r]);
            acc[r] = fmaf(xv.y, w1, acc[r]);
            acc[r] = fmaf(xv.z, w2, acc[r]);
            acc[r] = fmaf(xv.w, w3, acc[r]);
        }
    }

    #pragma unroll
    for (int r = 0; r < 32; r++) {
        int node = r0 + r;
        if (node < n) g_y[(size_t)node * D + tid] = acc[r] * g_dinv[node];
    }
}

// ---------------------------------------------------------------- pull aggregation + epilogue
// One block per node; thread t owns dim t.
// agg[c] = dinv[c] * (y[c] + sum_{r -> c} y[r]);  out = relu(agg + b)
__global__ void k_agg(const float* __restrict__ b, float* __restrict__ out, int n) {
    int node = blockIdx.x;
    if (node >= n) return;
    int tid = threadIdx.x;

    float acc = g_y[(size_t)node * D + tid];   // self-loop term
    int s = g_off[node];
    int e = g_off[node + 1];
    for (int i = s; i < e; i++) {
        int src = g_src[i];                     // broadcast load per warp
        acc += g_y[(size_t)src * D + tid];
    }
    float v = fmaf(acc, g_dinv[node], 0.f) + b[tid];
    out[(size_t)node * D + tid] = fmaxf(v, 0.f);
}

// ----------------------------------------------------------------
extern "C" void kernel_launch(void* const* d_in, const int* in_sizes, int n_in,
                              void* d_out, int out_size) {
    const float* x  = (const float*)d_in[0];
    const int*   ei = (const int*)  d_in[1];
    const float* W  = (const float*)d_in[2];
    const float* b  = (const float*)d_in[3];
    float*       out = (float*)d_out;

    int n = in_sizes[0] / D;
    int E = in_sizes[1] / 2;
    const int* row = ei;
    const int* col = ei + E;

    k_zero_deg<<<(n + 255) / 256, 256>>>(n);
    k_count  <<<(E + 255) / 256, 256>>>(col, E);
    k_scan   <<<1, 1024>>>(n);
    k_fill   <<<(E + 255) / 256, 256>>>(row, col, E);
    k_dinv   <<<(n + 255) / 256, 256>>>(n);
    k_gemm   <<<(n + 31) / 32, 128>>>(x, W, n);
    k_agg    <<<n, 128>>>(b, out, n);
}

// round 6
// speedup vs baseline: 1.6141x; 1.6141x over previous
#include <cuda_runtime.h>
#include <cuda_fp16.h>
#include <cuda_bf16.h>

#define N_MAX 100000
#define E_MAX 1600000
#define D 128
#define SCAN_B 1024
#define NB_MAX ((N_MAX + SCAN_B - 1) / SCAN_B)   // 98

// Scratch (allocation-free rule: __device__ globals)
__device__ int    g_deg[N_MAX];
__device__ int    g_off[N_MAX + 1];
__device__ int    g_cur[N_MAX];
__device__ int    g_src[E_MAX];
__device__ float  g_dinv[N_MAX];
__device__ int    g_bsum[NB_MAX];
__device__ int    g_bbase[NB_MAX];
__device__ __half g_yh[(size_t)N_MAX * D];   // 25.6 MB, L2-resident

// ---------------------------------------------------------------- deg zero
__global__ void k_zero_deg(int n) {
    int i = blockIdx.x * blockDim.x + threadIdx.x;
    if (i < n) g_deg[i] = 0;
}

// ---------------------------------------------------------------- deg count
__global__ void k_count(const int* __restrict__ col, int E) {
    int e = blockIdx.x * blockDim.x + threadIdx.x;
    if (e < E) atomicAdd(&g_deg[col[e]], 1);
}

// ---------------------------------------------------------------- pass 1: per-block sums of deg
__global__ void k_blocksum(int n) {
    __shared__ int warps[32];
    int tid = threadIdx.x, lane = tid & 31, w = tid >> 5;
    int i = blockIdx.x * SCAN_B + tid;
    int v = (i < n) ? g_deg[i] : 0;
    #pragma unroll
    for (int s = 16; s > 0; s >>= 1) v += __shfl_down_sync(0xffffffffu, v, s);
    if (lane == 0) warps[w] = v;
    __syncthreads();
    if (w == 0) {
        int x = warps[lane];
        #pragma unroll
        for (int s = 16; s > 0; s >>= 1) x += __shfl_down_sync(0xffffffffu, x, s);
        if (lane == 0) g_bsum[blockIdx.x] = x;
    }
}

// ---------------------------------------------------------------- pass 2: scan the <=128 block sums (1 block)
__global__ void k_scan_bsums(int nb, int n) {
    __shared__ int warps[4];
    int tid = threadIdx.x, lane = tid & 31, w = tid >> 5;
    int v = (tid < nb) ? g_bsum[tid] : 0;
    int inc = v;
    #pragma unroll
    for (int s = 1; s < 32; s <<= 1) {
        int t = __shfl_up_sync(0xffffffffu, inc, s);
        if (lane >= s) inc += t;
    }
    if (lane == 31) warps[w] = inc;
    __syncthreads();
    int wbase = 0;
    #pragma unroll
    for (int j = 0; j < 4; j++) if (j < w) wbase += warps[j];
    inc += wbase;
    if (tid < nb) g_bbase[tid] = inc - v;      // exclusive base per block
    if (tid == nb - 1) g_off[n] = inc;         // total edge count
}

// ---------------------------------------------------------------- pass 3: local scan + scatter offsets (+dinv fused)
__global__ void k_scatter_off(int n) {
    __shared__ int warps[32];
    int tid = threadIdx.x, lane = tid & 31, w = tid >> 5;
    int i = blockIdx.x * SCAN_B + tid;
    int v = (i < n) ? g_deg[i] : 0;
    int inc = v;
    #pragma unroll
    for (int s = 1; s < 32; s <<= 1) {
        int t = __shfl_up_sync(0xffffffffu, inc, s);
        if (lane >= s) inc += t;
    }
    if (lane == 31) warps[w] = inc;
    __syncthreads();
    if (w == 0) {
        int x = warps[lane];
        #pragma unroll
        for (int st = 1; st < 32; st <<= 1) {
            int t = __shfl_up_sync(0xffffffffu, x, st);
            if (lane >= st) x += t;
        }
        warps[lane] = x;
    }
    __syncthreads();
    int wbase = (w > 0) ? warps[w - 1] : 0;
    int ex = g_bbase[blockIdx.x] + inc + wbase - v;   // exclusive prefix
    if (i < n) {
        g_off[i]  = ex;
        g_cur[i]  = ex;
        g_dinv[i] = rsqrtf((float)(v + 1));           // +1 self-loop
    }
}

// ---------------------------------------------------------------- bucket fill (CSR by destination)
__global__ void k_fill(const int* __restrict__ row, const int* __restrict__ col, int E) {
    int e = blockIdx.x * blockDim.x + threadIdx.x;
    if (e < E) {
        int c = col[e];
        int pos = atomicAdd(&g_cur[c], 1);
        g_src[pos] = row[e];
    }
}

// ---------------------------------------------------------------- y = half(x @ W * dinv[row])
// 32 rows per 128-thread block; thread t owns output column t.
__global__ void k_gemm(const float* __restrict__ x, const float* __restrict__ W, int n) {
    __shared__ float xs[32 * D];
    int r0 = blockIdx.x * 32;
    int tid = threadIdx.x;

    for (int idx = tid; idx < 32 * D; idx += 128) {
        int r = idx >> 7, k = idx & 127;
        int node = r0 + r;
        xs[idx] = (node < n) ? x[(size_t)node * D + k] : 0.f;
    }
    __syncthreads();

    float acc[32];
    #pragma unroll
    for (int r = 0; r < 32; r++) acc[r] = 0.f;

    for (int k = 0; k < D; k += 4) {
        float w0 = W[(k + 0) * D + tid];
        float w1 = W[(k + 1) * D + tid];
        float w2 = W[(k + 2) * D + tid];
        float w3 = W[(k + 3) * D + tid];
        #pragma unroll
        for (int r = 0; r < 32; r++) {
            float4 xv = *reinterpret_cast<const float4*>(&xs[r * D + k]);
            acc[r] = fmaf(xv.x, w0, acc[r]);
            acc[r] = fmaf(xv.y, w1, acc[r]);
            acc[r] = fmaf(xv.z, w2, acc[r]);
            acc[r] = fmaf(xv.w, w3, acc[r]);
        }
    }

    #pragma unroll
    for (int r = 0; r < 32; r++) {
        int node = r0 + r;
        if (node < n)
            g_yh[(size_t)node * D + tid] = __float2half_rn(acc[r] * g_dinv[node]);
    }
}

// ---------------------------------------------------------------- pull aggregation + epilogue
// One WARP per node; lane owns 4 dims (uint2 = 4 halves). fp32 accumulate.
__global__ void k_agg(const float* __restrict__ b, float* __restrict__ out, int n) {
    int gw = (blockIdx.x * blockDim.x + threadIdx.x) >> 5;
    if (gw >= n) return;
    int lane = threadIdx.x & 31;

    const __half* yself = g_yh + (size_t)gw * D + lane * 4;
    uint2 u = *reinterpret_cast<const uint2*>(yself);
    float2 f0 = __half22float2(*reinterpret_cast<__half2*>(&u.x));
    float2 f1 = __half22float2(*reinterpret_cast<__half2*>(&u.y));
    float a0 = f0.x, a1 = f0.y, a2 = f1.x, a3 = f1.y;   // self-loop term

    int s = g_off[gw];
    int e = g_off[gw + 1];
    #pragma unroll 2
    for (int i = s; i < e; i++) {
        int src = g_src[i];                              // warp-broadcast load
        uint2 v = *reinterpret_cast<const uint2*>(g_yh + (size_t)src * D + lane * 4);
        float2 g0 = __half22float2(*reinterpret_cast<__half2*>(&v.x));
        float2 g1 = __half22float2(*reinterpret_cast<__half2*>(&v.y));
        a0 += g0.x; a1 += g0.y; a2 += g1.x; a3 += g1.y;
    }

    float di = g_dinv[gw];
    float4 bb = *reinterpret_cast<const float4*>(b + lane * 4);
    float4 o;
    o.x = fmaxf(fmaf(a0, di, bb.x), 0.f);
    o.y = fmaxf(fmaf(a1, di, bb.y), 0.f);
    o.z = fmaxf(fmaf(a2, di, bb.z), 0.f);
    o.w = fmaxf(fmaf(a3, di, bb.w), 0.f);
    *reinterpret_cast<float4*>(out + (size_t)gw * D + lane * 4) = o;
}

// ----------------------------------------------------------------
extern "C" void kernel_launch(void* const* d_in, const int* in_sizes, int n_in,
                              void* d_out, int out_size) {
    const float* x  = (const float*)d_in[0];
    const int*   ei = (const int*)  d_in[1];
    const float* W  = (const float*)d_in[2];
    const float* b  = (const float*)d_in[3];
    float*       out = (float*)d_out;

    int n = in_sizes[0] / D;
    int E = in_sizes[1] / 2;
    const int* row = ei;
    const int* col = ei + E;
    int nb = (n + SCAN_B - 1) / SCAN_B;

    k_zero_deg   <<<(n + 255) / 256, 256>>>(n);
    k_count      <<<(E + 255) / 256, 256>>>(col, E);
    k_blocksum   <<<nb, SCAN_B>>>(n);
    k_scan_bsums <<<1, 128>>>(nb, n);
    k_scatter_off<<<nb, SCAN_B>>>(n);
    k_fill       <<<(E + 255) / 256, 256>>>(row, col, E);
    k_gemm       <<<(n + 31) / 32, 128>>>(x, W, n);
    k_agg        <<<(n * 32 + 255) / 256, 256>>>(b, out, n);
}